// round 9
// baseline (speedup 1.0000x reference)
#include <cuda_runtime.h>

#define NS 512
#define HH 256
#define WW 256
#define HW (HH * WW)
#define EPSF 1e-6f
#define L2E 1.4426950408889634f
#define HPX (1.0f / 256.0f)

typedef unsigned long long u64;

__device__ float  g_red[512];
__device__ unsigned g_done;    // zero-init; last block restores to 0

__device__ __forceinline__ u64 ffma2(u64 a, u64 b, u64 c) {
    u64 d;
    asm("fma.rn.f32x2 %0, %1, %2, %3;" : "=l"(d) : "l"(a), "l"(b), "l"(c));
    return d;
}
__device__ __forceinline__ u64 fmul2(u64 a, u64 b) {
    u64 d;
    asm("mul.rn.f32x2 %0, %1, %2;" : "=l"(d) : "l"(a), "l"(b));
    return d;
}
__device__ __forceinline__ u64 pack2(float lo, float hi) {
    u64 d;
    asm("mov.b64 %0, {%1, %2};" : "=l"(d) : "f"(lo), "f"(hi));
    return d;
}
__device__ __forceinline__ void unpack2(u64 v, float& lo, float& hi) {
    asm("mov.b64 {%0, %1}, %2;" : "=f"(lo), "=f"(hi) : "l"(v));
}
__device__ __forceinline__ float ex2f(float x) {
    float r;
    asm("ex2.approx.ftz.f32 %0, %1;" : "=f"(r) : "f"(x));
    return r;
}
__device__ __forceinline__ void lds_v4f(unsigned addr, float4& v) {
    asm("ld.shared.v4.f32 {%0, %1, %2, %3}, [%4];"
        : "=f"(v.x), "=f"(v.y), "=f"(v.z), "=f"(v.w) : "r"(addr));
}
__device__ __forceinline__ void lds_v2u64(unsigned addr, u64& a, u64& b) {
    asm("ld.shared.v2.u64 {%0, %1}, [%2];" : "=l"(a), "=l"(b) : "r"(addr));
}
__device__ __forceinline__ u64 lds_u64(unsigned addr) {
    u64 a;
    asm("ld.shared.b64 %0, [%1];" : "=l"(a) : "r"(addr));
    return a;
}

// ---------------------------------------------------------------------------
// Single mega-kernel: 512 blocks x 256 threads. Block = half-row (128 px).
// Phase 1: inline per-stroke params (2 strokes/thread) -> shared (32 KB).
// Phase 2: 8 warps x 64-stroke slices; lane = 4 contiguous px; 4-px packed
//          geometric chain (2 EX2/stroke).
// Phase 3: smem reduction over the 8 warps (param region reused), then
//          canvas + sigmoid + out write + sq-err; last-done block -> loss.
// Stroke param layout (16 floats): {a,b,cc,K} {w0,w0} {w1,w1} {w2,w2} pad
// ---------------------------------------------------------------------------
__global__ void __launch_bounds__(256) mega_kernel(
    const float* __restrict__ canvas,
    const float* __restrict__ target,
    const float* __restrict__ offset,
    const float* __restrict__ sigma,
    const float* __restrict__ theta,
    const float* __restrict__ color,
    const float* __restrict__ alpha,
    float* __restrict__ out,
    int out_size)
{
    __shared__ float sh[NS * 16];   // 32 KB
    __shared__ float ws[8];
    __shared__ int lf;

    const int tid = threadIdx.x;
    const int lane = tid & 31;
    const int wid = tid >> 5;
    const int half = blockIdx.x & 1;
    const int row = blockIdx.x >> 1;
    const float rowy = (float)row * HPX;

    // ---- Phase 1: per-stroke params, 2 strokes per thread -----------------
    #pragma unroll
    for (int k = 0; k < 2; k++) {
        const int n = tid + 256 * k;
        const float ox = offset[2 * n + 0];
        const float oy = offset[2 * n + 1];
        const float sg0 = sigma[2 * n + 0];
        const float sg1 = sigma[2 * n + 1];
        const float th = theta[n];

        const float ratio = (float)WW / (float)HH;
        const float s0 = sg0 / ratio;
        float s, c;
        __sincosf(th, &s, &c);
        const float ia = __fdividef(0.5f, s0 * s0);
        const float ib = __fdividef(0.5f, sg1 * sg1);

        const float A = ia * c * c + ib * s * s;
        const float C = ia * s * s + ib * c * c;
        const float B = -2.0f * s * c * (ia + ib);

        const float Xm = (float)(WW - 1) / (float)WW;
        const float Ym = (float)(HH - 1) / (float)HH;
        const float x0d = -ox, x1d = Xm - ox;
        const float y0d = -oy, y1d = Ym - oy;

        float best = 3.4e38f, bdx = 0.0f, bdy = 0.0f;
        if (x0d <= 0.0f && x1d >= 0.0f && y0d <= 0.0f && y1d >= 0.0f) {
            best = 0.0f; bdx = 0.0f; bdy = 0.0f;
        }
        const float i2A = __fdividef(-0.5f, A);
        const float i2C = __fdividef(-0.5f, C);
        #pragma unroll
        for (int e = 0; e < 2; e++) {
            float ex = e ? x1d : x0d;
            float dyv = fminf(fmaxf(B * ex * i2C, y0d), y1d);
            float q = fmaf(A * ex, ex, fmaf(B * ex, dyv, C * dyv * dyv));
            if (q < best) { best = q; bdx = ex; bdy = dyv; }
        }
        #pragma unroll
        for (int e = 0; e < 2; e++) {
            float ey = e ? y1d : y0d;
            float dxv = fminf(fmaxf(B * ey * i2A, x0d), x1d);
            float q = fmaf(A * dxv, dxv, fmaf(B * dxv, ey, C * ey * ey));
            if (q < best) { best = q; bdx = dxv; bdy = ey; }
        }

        const float jx = floorf((bdx + ox) * (float)WW) - 1.0f;
        const float iy = floorf((bdy + oy) * (float)HH) - 1.0f;
        float mq = 3.4e38f;
        #pragma unroll
        for (int a2 = 0; a2 < 4; a2++) {
            float jj = fminf(fmaxf(jx + (float)a2, 0.0f), (float)(WW - 1));
            float dxv = jj * (1.0f / (float)WW) - ox;
            #pragma unroll
            for (int b2 = 0; b2 < 4; b2++) {
                float ii = fminf(fmaxf(iy + (float)b2, 0.0f), (float)(HH - 1));
                float dyv = ii * (1.0f / (float)HH) - oy;
                float q = fmaf(A * dxv, dxv, fmaf(B * dxv, dyv, C * dyv * dyv));
                mq = fminf(mq, q);
            }
        }

        const float maxpdf = __expf(-mq);
        const float scale = __fdividef(maxpdf, maxpdf + EPSF);
        const float al = alpha[n];
        const float w0 = al * color[3 * n + 0] * scale;
        const float w1 = al * color[3 * n + 1] * scale;
        const float w2 = al * color[3 * n + 2] * scale;

        const float aL  = -L2E * A;
        const float bL0 = 2.0f * L2E * A * ox;
        const float bL1 = -L2E * B;
        const float cL0 = L2E * (mq - A * ox * ox);
        const float cL1 = L2E * B * ox;
        const float cL2 = -L2E * C;
        const float K = exp2f(2.0f * aL * HPX * HPX);

        const float dy = rowy - oy;
        const float b = fmaf(bL1, dy, bL0);
        const float cc = fmaf(fmaf(cL2, dy, cL1), dy, cL0);

        float* d = &sh[n * 16];
        d[0] = aL;
        d[1] = b;
        d[2] = cc;
        d[3] = K;
        d[4] = w0;  d[5] = w0;
        d[6] = w1;  d[7] = w1;
        d[8] = w2;  d[9] = w2;
    }
    __syncthreads();

    // ---- Phase 2: main loop — warp wid handles strokes [wid*64, wid*64+64)
    const float x0 = (float)(half * 128 + lane * 4) * HPX;
    const float X1c = fmaf(2.0f * HPX, x0, HPX * HPX);

    u64 acc[3][2];
    #pragma unroll
    for (int ch = 0; ch < 3; ch++) {
        acc[ch][0] = 0ull;
        acc[ch][1] = 0ull;
    }

    const unsigned sbase = (unsigned)__cvta_generic_to_shared(sh) + wid * (64 * 64);

    #pragma unroll 4
    for (int sl = 0; sl < 64; sl++) {
        float4 q0;
        u64 ww0, ww1, ww2;
        lds_v4f(sbase + sl * 64, q0);
        lds_v2u64(sbase + sl * 64 + 16, ww0, ww1);
        ww2 = lds_u64(sbase + sl * 64 + 32);

        const float a = q0.x, b = q0.y, cc = q0.z, K = q0.w;
        float m0 = fmaf(fmaf(a, x0, b), x0, cc);
        float d0 = fmaf(a, X1c, b * HPX);
        float p0 = ex2f(m0);
        float t0 = ex2f(d0);
        float p1 = p0 * t0;
        float t0sq = t0 * t0;
        float r0 = t0sq * K;
        float r1 = r0 * (K * K);

        u64 pk0 = pack2(p0, p1);
        u64 T = pack2(r0, r1);
        u64 pk1 = fmul2(pk0, T);

        acc[0][0] = ffma2(pk0, ww0, acc[0][0]);
        acc[0][1] = ffma2(pk1, ww0, acc[0][1]);
        acc[1][0] = ffma2(pk0, ww1, acc[1][0]);
        acc[1][1] = ffma2(pk1, ww1, acc[1][1]);
        acc[2][0] = ffma2(pk0, ww2, acc[2][0]);
        acc[2][1] = ffma2(pk1, ww2, acc[2][1]);
    }

    // ---- Phase 3: cross-warp reduction (reuse sh), epilogue --------------
    __syncthreads();   // everyone done reading params
    {
        // sh2[w*384 + lane*12 + ch*4 + k], 8*384 = 3072 floats (12 KB)
        float* d = &sh[wid * 384 + lane * 12];
        #pragma unroll
        for (int ch = 0; ch < 3; ch++) {
            float v0, v1, v2, v3;
            unpack2(acc[ch][0], v0, v1);
            unpack2(acc[ch][1], v2, v3);
            d[ch * 4 + 0] = v0;
            d[ch * 4 + 1] = v1;
            d[ch * 4 + 2] = v2;
            d[ch * 4 + 3] = v3;
        }
    }
    __syncthreads();

    float sq = 0.0f;
    if (tid < 192) {
        #pragma unroll
        for (int vv = 0; vv < 2; vv++) {
            const int v = tid + 192 * vv;
            const int ch = v >> 7;
            const int p = v & 127;
            const int off = (p >> 2) * 12 + ch * 4 + (p & 3);
            float sum = 0.0f;
            #pragma unroll
            for (int w = 0; w < 8; w++)
                sum += sh[w * 384 + off];
            const int idx = ch * HW + row * WW + half * 128 + p;
            float z = canvas[idx] + sum;
            float o = __fdividef(1.0f, 1.0f + __expf(-z));
            out[idx] = o;
            float dd = o - target[idx];
            sq = fmaf(dd, dd, sq);
        }
    }

    #pragma unroll
    for (int o2 = 16; o2 > 0; o2 >>= 1)
        sq += __shfl_down_sync(0xffffffffu, sq, o2);
    if (lane == 0) ws[wid] = sq;
    __syncthreads();
    if (tid == 0) {
        float t2 = 0.f;
        #pragma unroll
        for (int k = 0; k < 8; k++) t2 += ws[k];
        g_red[blockIdx.x] = t2;
        __threadfence();
        unsigned prev = atomicAdd(&g_done, 1u);
        lf = (prev == 511u) ? 1 : 0;
    }
    __syncthreads();

    // ---- Final loss (last-done block) ------------------------------------
    if (lf) {
        float pa = g_red[tid] + g_red[tid + 256];
        float pb = 0.f, pc = 0.f;
        #pragma unroll
        for (int k = 0; k < 2; k++) {
            int nn = tid + 256 * k;
            pb += fabsf(1.0f - __fdividef(sigma[2 * nn], sigma[2 * nn + 1]));
            pc += fabsf(alpha[nn]);
        }
        #pragma unroll
        for (int o2 = 16; o2 > 0; o2 >>= 1) {
            pa += __shfl_down_sync(0xffffffffu, pa, o2);
            pb += __shfl_down_sync(0xffffffffu, pb, o2);
            pc += __shfl_down_sync(0xffffffffu, pc, o2);
        }
        if (lane == 0) {
            sh[wid] = pa;
            sh[8 + wid] = pb;
            sh[16 + wid] = pc;
        }
        __syncthreads();
        if (tid == 0) {
            float sa = 0.f, sb = 0.f, sc = 0.f;
            #pragma unroll
            for (int k = 0; k < 8; k++) {
                sa += sh[k];
                sb += sh[8 + k];
                sc += sh[16 + k];
            }
            float mse = sa / (float)(3 * HW);
            float sharp = sb * (0.001f / (float)NS);
            float transp = -sc * (0.001f / (float)NS);
            float psnr = -10.0f * log10f(mse + 1e-12f);
            float loss = mse + transp + sharp - psnr / 30.0f;
            if (out_size > 3 * HW) out[3 * HW] = loss;
            g_done = 0u;   // restore state for next graph replay
        }
    }
}

// ---------------------------------------------------------------------------
extern "C" void kernel_launch(void* const* d_in, const int* in_sizes, int n_in,
                              void* d_out, int out_size)
{
    const float* canvas = (const float*)d_in[0];
    const float* target = (const float*)d_in[1];
    const float* offset = (const float*)d_in[2];
    const float* sigma  = (const float*)d_in[3];
    const float* theta  = (const float*)d_in[4];
    const float* color  = (const float*)d_in[5];
    const float* alpha  = (const float*)d_in[6];
    float* out = (float*)d_out;

    mega_kernel<<<512, 256>>>(canvas, target, offset, sigma, theta, color,
                              alpha, out, out_size);
}

// round 10
// speedup vs baseline: 1.0152x; 1.0152x over previous
#include <cuda_runtime.h>

#define NS 512
#define HH 256
#define WW 256
#define HW (HH * WW)
#define EPSF 1e-6f
#define L2E 1.4426950408889634f
#define HPX (1.0f / 256.0f)

typedef unsigned long long u64;

__device__ float  g_red[256];
__device__ unsigned g_done;    // zero-init; last block restores to 0

__device__ __forceinline__ u64 ffma2(u64 a, u64 b, u64 c) {
    u64 d;
    asm("fma.rn.f32x2 %0, %1, %2, %3;" : "=l"(d) : "l"(a), "l"(b), "l"(c));
    return d;
}
__device__ __forceinline__ u64 fmul2(u64 a, u64 b) {
    u64 d;
    asm("mul.rn.f32x2 %0, %1, %2;" : "=l"(d) : "l"(a), "l"(b));
    return d;
}
__device__ __forceinline__ u64 pack2(float lo, float hi) {
    u64 d;
    asm("mov.b64 %0, {%1, %2};" : "=l"(d) : "f"(lo), "f"(hi));
    return d;
}
__device__ __forceinline__ void unpack2(u64 v, float& lo, float& hi) {
    asm("mov.b64 {%0, %1}, %2;" : "=f"(lo), "=f"(hi) : "l"(v));
}
__device__ __forceinline__ float ex2f(float x) {
    float r;
    asm("ex2.approx.ftz.f32 %0, %1;" : "=f"(r) : "f"(x));
    return r;
}
__device__ __forceinline__ void lds_v4f(unsigned addr, float4& v) {
    asm("ld.shared.v4.f32 {%0, %1, %2, %3}, [%4];"
        : "=f"(v.x), "=f"(v.y), "=f"(v.z), "=f"(v.w) : "r"(addr));
}
__device__ __forceinline__ void lds_v2u64(unsigned addr, u64& a, u64& b) {
    asm("ld.shared.v2.u64 {%0, %1}, [%2];" : "=l"(a), "=l"(b) : "r"(addr));
}

// ---------------------------------------------------------------------------
// Single kernel: 256 blocks x 512 threads. Block = one image row (256 px).
// Phase 1: per-stroke params inline, 1 stroke/thread -> shared (32 KB).
// Phase 2: 16 warps x 32-stroke slices; lane owns 8 contiguous px; 8-px
//          packed geometric chain (2 EX2/stroke), 12 ffma2 accumulation.
// Phase 3: 16-warp smem reduction (48 KB, unioned with params), fused
//          canvas+sigmoid+out+MSE epilogue; last-done block -> loss.
// Param layout (16 floats): {a,b,cc,K} {K4,K4,w0,w0} {w1,w1,w2,w2} {bh,...}
// ---------------------------------------------------------------------------
__global__ void __launch_bounds__(512) mega_kernel(
    const float* __restrict__ canvas,
    const float* __restrict__ target,
    const float* __restrict__ offset,
    const float* __restrict__ sigma,
    const float* __restrict__ theta,
    const float* __restrict__ color,
    const float* __restrict__ alpha,
    float* __restrict__ out,
    int out_size)
{
    __shared__ float sh[12288];   // 48 KB: params (32 KB) then reduction buf

    const int tid = threadIdx.x;
    const int lane = tid & 31;
    const int wid = tid >> 5;
    const int row = blockIdx.x;
    const float rowy = (float)row * HPX;

    // ---- Phase 1: per-stroke params, one stroke per thread ----------------
    {
        const int n = tid;
        const float ox = offset[2 * n + 0];
        const float oy = offset[2 * n + 1];
        const float sg0 = sigma[2 * n + 0];
        const float sg1 = sigma[2 * n + 1];
        const float th = theta[n];

        const float ratio = (float)WW / (float)HH;
        const float s0 = sg0 / ratio;
        float s, c;
        __sincosf(th, &s, &c);
        const float ia = __fdividef(0.5f, s0 * s0);
        const float ib = __fdividef(0.5f, sg1 * sg1);

        const float A = ia * c * c + ib * s * s;
        const float C = ia * s * s + ib * c * c;
        const float B = -2.0f * s * c * (ia + ib);

        const float Xm = (float)(WW - 1) / (float)WW;
        const float Ym = (float)(HH - 1) / (float)HH;
        const float x0d = -ox, x1d = Xm - ox;
        const float y0d = -oy, y1d = Ym - oy;

        float best = 3.4e38f, bdx = 0.0f, bdy = 0.0f;
        if (x0d <= 0.0f && x1d >= 0.0f && y0d <= 0.0f && y1d >= 0.0f) {
            best = 0.0f; bdx = 0.0f; bdy = 0.0f;
        }
        const float i2A = __fdividef(-0.5f, A);
        const float i2C = __fdividef(-0.5f, C);
        #pragma unroll
        for (int e = 0; e < 2; e++) {
            float ex = e ? x1d : x0d;
            float dyv = fminf(fmaxf(B * ex * i2C, y0d), y1d);
            float q = fmaf(A * ex, ex, fmaf(B * ex, dyv, C * dyv * dyv));
            if (q < best) { best = q; bdx = ex; bdy = dyv; }
        }
        #pragma unroll
        for (int e = 0; e < 2; e++) {
            float ey = e ? y1d : y0d;
            float dxv = fminf(fmaxf(B * ey * i2A, x0d), x1d);
            float q = fmaf(A * dxv, dxv, fmaf(B * dxv, ey, C * ey * ey));
            if (q < best) { best = q; bdx = dxv; bdy = ey; }
        }

        const float jx = floorf((bdx + ox) * (float)WW) - 1.0f;
        const float iy = floorf((bdy + oy) * (float)HH) - 1.0f;
        float mq = 3.4e38f;
        #pragma unroll
        for (int a2 = 0; a2 < 4; a2++) {
            float jj = fminf(fmaxf(jx + (float)a2, 0.0f), (float)(WW - 1));
            float dxv = jj * (1.0f / (float)WW) - ox;
            #pragma unroll
            for (int b2 = 0; b2 < 4; b2++) {
                float ii = fminf(fmaxf(iy + (float)b2, 0.0f), (float)(HH - 1));
                float dyv = ii * (1.0f / (float)HH) - oy;
                float q = fmaf(A * dxv, dxv, fmaf(B * dxv, dyv, C * dyv * dyv));
                mq = fminf(mq, q);
            }
        }

        const float maxpdf = __expf(-mq);
        const float scale = __fdividef(maxpdf, maxpdf + EPSF);
        const float al = alpha[n];
        const float w0 = al * color[3 * n + 0] * scale;
        const float w1 = al * color[3 * n + 1] * scale;
        const float w2 = al * color[3 * n + 2] * scale;

        const float aL  = -L2E * A;
        const float bL0 = 2.0f * L2E * A * ox;
        const float bL1 = -L2E * B;
        const float cL0 = L2E * (mq - A * ox * ox);
        const float cL1 = L2E * B * ox;
        const float cL2 = -L2E * C;
        const float K = exp2f(2.0f * aL * HPX * HPX);
        const float K4 = (K * K) * (K * K);

        const float dy = rowy - oy;
        const float b = fmaf(bL1, dy, bL0);
        const float cc = fmaf(fmaf(cL2, dy, cL1), dy, cL0);

        float* d = &sh[n * 16];
        d[0] = aL;
        d[1] = b;
        d[2] = cc;
        d[3] = K;
        d[4] = K4;  d[5] = K4;
        d[6] = w0;  d[7] = w0;
        d[8] = w1;  d[9] = w1;
        d[10] = w2; d[11] = w2;
        d[12] = b * HPX;           // bh
    }
    __syncthreads();

    // ---- Phase 2: warp wid handles strokes [wid*32, wid*32+32) ------------
    const float x0 = (float)(lane * 8) * HPX;
    const float X1c = fmaf(2.0f * HPX, x0, HPX * HPX);

    u64 acc[3][4];
    #pragma unroll
    for (int ch = 0; ch < 3; ch++)
        #pragma unroll
        for (int k = 0; k < 4; k++) acc[ch][k] = 0ull;

    const unsigned sbase = (unsigned)__cvta_generic_to_shared(sh) + wid * (32 * 64);

    #pragma unroll 4
    for (int sl = 0; sl < 32; sl++) {
        float4 q0;
        u64 K4v, ww0, ww1, ww2;
        float bh;
        lds_v4f(sbase + sl * 64, q0);
        lds_v2u64(sbase + sl * 64 + 16, K4v, ww0);
        lds_v2u64(sbase + sl * 64 + 32, ww1, ww2);
        asm("ld.shared.f32 %0, [%1];" : "=f"(bh) : "r"(sbase + sl * 64 + 48));

        const float a = q0.x, b = q0.y, cc = q0.z, K = q0.w;
        float m0 = fmaf(fmaf(a, x0, b), x0, cc);
        float d0 = fmaf(a, X1c, bh);
        float p0 = ex2f(m0);
        float t0 = ex2f(d0);
        float p1 = p0 * t0;
        float t0sq = t0 * t0;
        float r0 = t0sq * K;
        float r1 = r0 * (K * K);

        u64 pk0 = pack2(p0, p1);
        u64 T = pack2(r0, r1);
        u64 pk1 = fmul2(pk0, T);
        u64 T2 = fmul2(T, K4v);
        u64 pk2 = fmul2(pk1, T2);
        u64 T3 = fmul2(T2, K4v);
        u64 pk3 = fmul2(pk2, T3);

        acc[0][0] = ffma2(pk0, ww0, acc[0][0]);
        acc[0][1] = ffma2(pk1, ww0, acc[0][1]);
        acc[0][2] = ffma2(pk2, ww0, acc[0][2]);
        acc[0][3] = ffma2(pk3, ww0, acc[0][3]);
        acc[1][0] = ffma2(pk0, ww1, acc[1][0]);
        acc[1][1] = ffma2(pk1, ww1, acc[1][1]);
        acc[1][2] = ffma2(pk2, ww1, acc[1][2]);
        acc[1][3] = ffma2(pk3, ww1, acc[1][3]);
        acc[2][0] = ffma2(pk0, ww2, acc[2][0]);
        acc[2][1] = ffma2(pk1, ww2, acc[2][1]);
        acc[2][2] = ffma2(pk2, ww2, acc[2][2]);
        acc[2][3] = ffma2(pk3, ww2, acc[2][3]);
    }

    // ---- Phase 3: 16-warp reduction in smem, fused epilogue ---------------
    __syncthreads();   // all param reads done; sh becomes reduction buffer
    {
        // buf[w*768 + ch*256 + lane*8 + k]  (px-major, conflict-free)
        float* d = &sh[wid * 768 + lane * 8];
        #pragma unroll
        for (int ch = 0; ch < 3; ch++) {
            float v0, v1, v2, v3, v4, v5, v6, v7;
            unpack2(acc[ch][0], v0, v1);
            unpack2(acc[ch][1], v2, v3);
            unpack2(acc[ch][2], v4, v5);
            unpack2(acc[ch][3], v6, v7);
            float4* p4 = (float4*)(d + ch * 256);
            p4[0] = make_float4(v0, v1, v2, v3);
            p4[1] = make_float4(v4, v5, v6, v7);
        }
    }
    __syncthreads();

    float sq = 0.0f;
    {
        // 768 values (3 ch x 256 px); threads 0..511 take v=tid, tid<256 also v=tid+512
        #pragma unroll
        for (int vv = 0; vv < 2; vv++) {
            const int v = tid + 512 * vv;
            if (v < 768) {
                const int ch = v >> 8;
                const int p = v & 255;
                const int off = ch * 256 + p;
                float sum = 0.0f;
                #pragma unroll
                for (int w = 0; w < 16; w++)
                    sum += sh[w * 768 + off];
                const int idx = ch * HW + row * WW + p;
                float z = canvas[idx] + sum;
                float o = __fdividef(1.0f, 1.0f + __expf(-z));
                out[idx] = o;
                float dd = o - target[idx];
                sq = fmaf(dd, dd, sq);
            }
        }
    }

    #pragma unroll
    for (int o2 = 16; o2 > 0; o2 >>= 1)
        sq += __shfl_down_sync(0xffffffffu, sq, o2);
    __syncthreads();          // all buf reads done; reuse sh[0..17]
    if (lane == 0) sh[wid] = sq;
    __syncthreads();
    if (tid == 0) {
        float t2 = 0.f;
        #pragma unroll
        for (int k = 0; k < 16; k++) t2 += sh[k];
        g_red[row] = t2;
        __threadfence();
        unsigned prev = atomicAdd(&g_done, 1u);
        sh[17] = (prev == 255u) ? 1.0f : 0.0f;
    }
    __syncthreads();

    // ---- Final loss (last-done block) ------------------------------------
    if (sh[17] != 0.0f) {
        float pa = (tid < 256) ? g_red[tid] : 0.0f;
        float pb = fabsf(1.0f - __fdividef(sigma[2 * tid], sigma[2 * tid + 1]));
        float pc = fabsf(alpha[tid]);
        #pragma unroll
        for (int o2 = 16; o2 > 0; o2 >>= 1) {
            pa += __shfl_down_sync(0xffffffffu, pa, o2);
            pb += __shfl_down_sync(0xffffffffu, pb, o2);
            pc += __shfl_down_sync(0xffffffffu, pc, o2);
        }
        __syncthreads();
        if (lane == 0) {
            sh[wid] = pa;
            sh[16 + wid] = pb;
            sh[32 + wid] = pc;
        }
        __syncthreads();
        if (tid == 0) {
            float sa = 0.f, sb = 0.f, sc = 0.f;
            #pragma unroll
            for (int k = 0; k < 16; k++) {
                sa += sh[k];
                sb += sh[16 + k];
                sc += sh[32 + k];
            }
            float mse = sa / (float)(3 * HW);
            float sharp = sb * (0.001f / (float)NS);
            float transp = -sc * (0.001f / (float)NS);
            float psnr = -10.0f * log10f(mse + 1e-12f);
            float loss = mse + transp + sharp - psnr / 30.0f;
            if (out_size > 3 * HW) out[3 * HW] = loss;
            g_done = 0u;   // restore state for next graph replay
        }
    }
}

// ---------------------------------------------------------------------------
extern "C" void kernel_launch(void* const* d_in, const int* in_sizes, int n_in,
                              void* d_out, int out_size)
{
    const float* canvas = (const float*)d_in[0];
    const float* target = (const float*)d_in[1];
    const float* offset = (const float*)d_in[2];
    const float* sigma  = (const float*)d_in[3];
    const float* theta  = (const float*)d_in[4];
    const float* color  = (const float*)d_in[5];
    const float* alpha  = (const float*)d_in[6];
    float* out = (float*)d_out;

    mega_kernel<<<256, 512>>>(canvas, target, offset, sigma, theta, color,
                              alpha, out, out_size);
}